// round 1
// baseline (speedup 1.0000x reference)
#include <cuda_runtime.h>
#include <cstdint>
#include <cstddef>

// ---------------------------------------------------------------------------
// SpanElectraGeneratorPredictionHead — fp32, f32x2-packed SGEMMs
//
// Pipeline:
//   1) gather:   Ag[256][1536] = [lh | rh] per span
//   2) posw:     P[20][768] = pos_emb @ W1[1536:1736] + b1
//   3) gemm(split-K=8): Upart[8][256][768] = Ag @ W1[0:1536]
//   4) fuse1:    h1[5120][768] = LN(gelu(sum_z Upart + P))
//   5) gemm:     pre2 = h1 @ W2
//   6) fuse2:    h2 = LN(gelu(pre2 + b2))
//   7) gemm:     h3[5120][128] = h2 @ Wp + bp
//   8) gemm NT:  out[5120][30522] = h3 @ Wdec^T
// ---------------------------------------------------------------------------

#define DIM    768
#define SEQ    512
#define BSZ    8
#define NPAIR  32
#define SPANS  256
#define PE     200
#define SPAN_L 20
#define ROWS   5120      // SPANS*SPAN_L
#define EMB    128
#define VOCAB  30522
#define KSPLIT 8
#define K1LEN  192       // 1536/KSPLIT

// scratch (static device allocations — no cudaMalloc allowed)
__device__ float g_Ag[SPANS * 2 * DIM];
__device__ float g_P[SPAN_L * DIM];
__device__ float g_Upart[KSPLIT * SPANS * DIM];
__device__ float g_h1[ROWS * DIM];
__device__ float g_pre2[ROWS * DIM];
__device__ float g_h2[ROWS * DIM];
__device__ float g_h3[ROWS * EMB];

// ---------------- packed f32x2 helpers (sm_103a FFMA2 path) ----------------
__device__ __forceinline__ unsigned long long pack2(float x, float y) {
    unsigned long long r;
    asm("mov.b64 %0, {%1, %2};" : "=l"(r)
        : "r"(__float_as_uint(x)), "r"(__float_as_uint(y)));
    return r;
}
__device__ __forceinline__ void unpack2(unsigned long long v, float& x, float& y) {
    unsigned a, b;
    asm("mov.b64 {%0, %1}, %2;" : "=r"(a), "=r"(b) : "l"(v));
    x = __uint_as_float(a);
    y = __uint_as_float(b);
}
__device__ __forceinline__ void fma2(unsigned long long& d,
                                     unsigned long long a, unsigned long long b) {
    asm("fma.rn.f32x2 %0, %1, %2, %0;" : "+l"(d) : "l"(a), "l"(b));
}

// ---------------------------------------------------------------------------
// 1) gather span endpoints -> Ag[s][0:768]=lh, Ag[s][768:1536]=rh
// ---------------------------------------------------------------------------
__global__ void __launch_bounds__(256) gather_kernel(const float* __restrict__ H,
                                                     const int* __restrict__ pairs) {
    int s = blockIdx.x;                 // 0..255
    int b = s / NPAIR;
    int i0 = pairs[s * 2 + 0];
    int i1 = pairs[s * 2 + 1];
    const float* h0 = H + ((size_t)b * SEQ + i0) * DIM;
    const float* h1 = H + ((size_t)b * SEQ + i1) * DIM;
    float* dst = g_Ag + (size_t)s * (2 * DIM);
    for (int i = threadIdx.x; i < DIM; i += 256) {
        dst[i]       = h0[i];
        dst[DIM + i] = h1[i];
    }
}

// ---------------------------------------------------------------------------
// 2) P[l][n] = b1[n] + sum_k pos_emb[l][k] * W1[1536+k][n]
// ---------------------------------------------------------------------------
__global__ void __launch_bounds__(DIM) posw_kernel(const float* __restrict__ pos_emb,
                                                   const float* __restrict__ W1,
                                                   const float* __restrict__ b1) {
    int l = blockIdx.x;      // 0..19
    int n = threadIdx.x;     // 0..767
    __shared__ float pe[PE];
    for (int i = threadIdx.x; i < PE; i += blockDim.x) pe[i] = pos_emb[l * PE + i];
    __syncthreads();
    float acc = b1[n];
    const float* Wc = W1 + (size_t)(2 * DIM) * DIM + n;
    #pragma unroll 4
    for (int k = 0; k < PE; ++k) acc = fmaf(pe[k], Wc[(size_t)k * DIM], acc);
    g_P[l * DIM + n] = acc;
}

// ---------------------------------------------------------------------------
// Generic f32x2 SGEMM body. A row-major [M][lda] (K-contig). B either
// row-major [K][ldb] (NN) or row-major [N][ldb] K-contig (NT / TRANSB).
// C row-major [M][ldc]. 256 threads, 16x16 layout, TMxTN per-thread tile.
// Accumulators are m-pair packed f32x2: loaded straight from the k-major
// smem A tile as 64-bit (no pack); only B scalar is replicated (alu pipe,
// overlaps fma pipe).
// ---------------------------------------------------------------------------
template<int BM, int BN, int BK, int TM, int TN, bool TRANSB>
__device__ __forceinline__ void gemm_body(
    const float* __restrict__ A, int lda,
    const float* __restrict__ B, int ldb,
    const float* __restrict__ bias,
    float* __restrict__ C, int ldc,
    int N, int klen)
{
    __shared__ float As[BK][BM];   // k-major
    __shared__ float Bs[BK][BN];   // k-major
    const int tid = threadIdx.x;
    const int tx = tid & 15;
    const int ty = tid >> 4;
    const int m0 = blockIdx.y * BM;
    const int n0 = blockIdx.x * BN;
    const int k0 = blockIdx.z * klen;

    unsigned long long acc[TM / 2][TN];
    #pragma unroll
    for (int i = 0; i < TM / 2; ++i)
        #pragma unroll
        for (int j = 0; j < TN; ++j) acc[i][j] = 0ull;

    for (int kk = 0; kk < klen; kk += BK) {
        // --- load A tile (transpose-store to k-major) ---
        #pragma unroll
        for (int i = 0; i < (BM * BK) / 1024; ++i) {
            int q   = tid + i * 256;
            int row = q / (BK / 4);
            int kc  = (q % (BK / 4)) * 4;
            float4 v = *(const float4*)&A[(size_t)(m0 + row) * lda + (k0 + kk + kc)];
            As[kc + 0][row] = v.x; As[kc + 1][row] = v.y;
            As[kc + 2][row] = v.z; As[kc + 3][row] = v.w;
        }
        // --- load B tile ---
        if (!TRANSB) {
            #pragma unroll
            for (int i = 0; i < (BK * BN) / 1024; ++i) {
                int q  = tid + i * 256;
                int kr = q / (BN / 4);
                int nc = (q % (BN / 4)) * 4;
                *(float4*)&Bs[kr][nc] =
                    *(const float4*)&B[(size_t)(k0 + kk + kr) * ldb + (n0 + nc)];
            }
        } else {
            #pragma unroll
            for (int i = 0; i < (BK * BN) / 1024; ++i) {
                int q   = tid + i * 256;
                int row = q / (BK / 4);            // n within tile
                int kc  = (q % (BK / 4)) * 4;
                int ng  = n0 + row; if (ng > N - 1) ng = N - 1;   // clamp edge
                float4 v = *(const float4*)&B[(size_t)ng * ldb + (k0 + kk + kc)];
                Bs[kc + 0][row] = v.x; Bs[kc + 1][row] = v.y;
                Bs[kc + 2][row] = v.z; Bs[kc + 3][row] = v.w;
            }
        }
        __syncthreads();

        #pragma unroll
        for (int k = 0; k < BK; ++k) {
            unsigned long long a2[TM / 2];
            #pragma unroll
            for (int i = 0; i < TM / 2; ++i)
                a2[i] = *(const unsigned long long*)&As[k][ty * TM + 2 * i];
            #pragma unroll
            for (int j = 0; j < TN; ++j) {
                float bv = Bs[k][tx * TN + j];
                unsigned long long b2 = pack2(bv, bv);
                #pragma unroll
                for (int i = 0; i < TM / 2; ++i) fma2(acc[i][j], a2[i], b2);
            }
        }
        __syncthreads();
    }

    // --- epilogue ---
    #pragma unroll
    for (int j = 0; j < TN; ++j) {
        int n = n0 + tx * TN + j;
        if (TRANSB && n >= N) continue;
        float bv = bias ? bias[n] : 0.0f;
        #pragma unroll
        for (int i = 0; i < TM / 2; ++i) {
            float lo, hi;
            unpack2(acc[i][j], lo, hi);
            int m = m0 + ty * TM + 2 * i;
            C[(size_t)m * ldc + n]       = lo + bv;
            C[(size_t)(m + 1) * ldc + n] = hi + bv;
        }
    }
}

// wrappers (device code may take addresses of __device__ globals)
__global__ void __launch_bounds__(256) k_gemm_span(const float* __restrict__ W1) {
    gemm_body<64, 128, 16, 4, 8, false>(
        g_Ag, 2 * DIM, W1, DIM, nullptr,
        g_Upart + (size_t)blockIdx.z * SPANS * DIM, DIM, DIM, K1LEN);
}
__global__ void __launch_bounds__(256) k_gemm_h1W2(const float* __restrict__ W2) {
    gemm_body<128, 128, 16, 8, 8, false>(
        g_h1, DIM, W2, DIM, nullptr, g_pre2, DIM, DIM, DIM);
}
__global__ void __launch_bounds__(256) k_gemm_proj(const float* __restrict__ Wp,
                                                   const float* __restrict__ bp) {
    gemm_body<64, 128, 16, 4, 8, false>(
        g_h2, DIM, Wp, EMB, bp, g_h3, EMB, EMB, DIM);
}
__global__ void __launch_bounds__(256) k_gemm_vocab(const float* __restrict__ Wdec,
                                                    float* __restrict__ out) {
    gemm_body<128, 128, 32, 8, 8, true>(
        g_h3, EMB, Wdec, EMB, nullptr, out, VOCAB, VOCAB, EMB);
}

// ---------------------------------------------------------------------------
// gelu + layernorm fusions (one block per row, 256 threads, 3 cols each)
// ---------------------------------------------------------------------------
__device__ __forceinline__ float gelu_exact(float x) {
    return 0.5f * x * (1.0f + erff(x * 0.70710678118654752f));
}

__global__ void __launch_bounds__(256) fuse_ln1(const float* __restrict__ g,
                                                const float* __restrict__ be) {
    int r = blockIdx.x;
    int s = r / SPAN_L;
    int l = r % SPAN_L;
    __shared__ float shs[8], shq[8];
    float v[3];
    float sum = 0.f, sq = 0.f;
    #pragma unroll
    for (int j = 0; j < 3; ++j) {
        int n = threadIdx.x + j * 256;
        float x = g_P[l * DIM + n];
        #pragma unroll
        for (int z = 0; z < KSPLIT; ++z)
            x += g_Upart[(size_t)z * SPANS * DIM + (size_t)s * DIM + n];
        float ge = gelu_exact(x);
        v[j] = ge;
        sum += ge;
        sq  += ge * ge;
    }
    #pragma unroll
    for (int o = 16; o > 0; o >>= 1) {
        sum += __shfl_xor_sync(0xffffffffu, sum, o);
        sq  += __shfl_xor_sync(0xffffffffu, sq, o);
    }
    if ((threadIdx.x & 31) == 0) { shs[threadIdx.x >> 5] = sum; shq[threadIdx.x >> 5] = sq; }
    __syncthreads();
    float ts = 0.f, tq = 0.f;
    #pragma unroll
    for (int w = 0; w < 8; ++w) { ts += shs[w]; tq += shq[w]; }
    float mean = ts * (1.0f / DIM);
    float var  = tq * (1.0f / DIM) - mean * mean;
    float rstd = rsqrtf(var + 1e-12f);
    #pragma unroll
    for (int j = 0; j < 3; ++j) {
        int n = threadIdx.x + j * 256;
        g_h1[(size_t)r * DIM + n] = (v[j] - mean) * rstd * g[n] + be[n];
    }
}

__global__ void __launch_bounds__(256) fuse_ln2(const float* __restrict__ bias,
                                                const float* __restrict__ g,
                                                const float* __restrict__ be) {
    int r = blockIdx.x;
    __shared__ float shs[8], shq[8];
    float v[3];
    float sum = 0.f, sq = 0.f;
    #pragma unroll
    for (int j = 0; j < 3; ++j) {
        int n = threadIdx.x + j * 256;
        float x = g_pre2[(size_t)r * DIM + n] + bias[n];
        float ge = gelu_exact(x);
        v[j] = ge;
        sum += ge;
        sq  += ge * ge;
    }
    #pragma unroll
    for (int o = 16; o > 0; o >>= 1) {
        sum += __shfl_xor_sync(0xffffffffu, sum, o);
        sq  += __shfl_xor_sync(0xffffffffu, sq, o);
    }
    if ((threadIdx.x & 31) == 0) { shs[threadIdx.x >> 5] = sum; shq[threadIdx.x >> 5] = sq; }
    __syncthreads();
    float ts = 0.f, tq = 0.f;
    #pragma unroll
    for (int w = 0; w < 8; ++w) { ts += shs[w]; tq += shq[w]; }
    float mean = ts * (1.0f / DIM);
    float var  = tq * (1.0f / DIM) - mean * mean;
    float rstd = rsqrtf(var + 1e-12f);
    #pragma unroll
    for (int j = 0; j < 3; ++j) {
        int n = threadIdx.x + j * 256;
        g_h2[(size_t)r * DIM + n] = (v[j] - mean) * rstd * g[n] + be[n];
    }
}

// ---------------------------------------------------------------------------
// launch
// ---------------------------------------------------------------------------
extern "C" void kernel_launch(void* const* d_in, const int* in_sizes, int n_in,
                              void* d_out, int out_size) {
    const float* H       = (const float*)d_in[0];   // [8,512,768]
    const int*   pairs   = (const int*)  d_in[1];   // [8,32,2]
    const float* pos_emb = (const float*)d_in[2];   // [20,200]
    const float* W1      = (const float*)d_in[3];   // [1736,768]
    const float* b1      = (const float*)d_in[4];
    const float* g1      = (const float*)d_in[5];
    const float* be1     = (const float*)d_in[6];
    const float* W2      = (const float*)d_in[7];   // [768,768]
    const float* b2      = (const float*)d_in[8];
    const float* g2      = (const float*)d_in[9];
    const float* be2     = (const float*)d_in[10];
    const float* Wp      = (const float*)d_in[11];  // [768,128]
    const float* bp      = (const float*)d_in[12];
    const float* Wdec    = (const float*)d_in[13];  // [30522,128]
    float* out = (float*)d_out;                     // [256,20,30522]

    gather_kernel<<<SPANS, 256>>>(H, pairs);
    posw_kernel<<<SPAN_L, DIM>>>(pos_emb, W1, b1);
    k_gemm_span<<<dim3(DIM / 128, SPANS / 64, KSPLIT), 256>>>(W1);
    fuse_ln1<<<ROWS, 256>>>(g1, be1);
    k_gemm_h1W2<<<dim3(DIM / 128, ROWS / 128, 1), 256>>>(W2);
    fuse_ln2<<<ROWS, 256>>>(b2, g2, be2);
    k_gemm_proj<<<dim3(1, ROWS / 64, 1), 256>>>(Wp, bp);
    k_gemm_vocab<<<dim3((VOCAB + 127) / 128, ROWS / 128, 1), 256>>>(Wdec, out);
}

// round 4
// speedup vs baseline: 2.2972x; 2.2972x over previous
#include <cuda_runtime.h>
#include <cuda_bf16.h>
#include <cstdint>
#include <cstddef>

// ---------------------------------------------------------------------------
// SpanElectraGeneratorPredictionHead
//   small GEMMs: FFMA2 (fp32 exact)
//   vocab GEMM:  mma.sync bf16 HMMA, split-bf16 K'=384 error compensation
//     A' = [hi(h3) | hi | lo],  B' = [hi(Wdec) | lo | hi]  (fp32 accumulate)
// ---------------------------------------------------------------------------

#define DIM    768
#define SEQ    512
#define NPAIR  32
#define SPANS  256
#define PE     200
#define SPAN_L 20
#define ROWS   5120
#define EMB    128
#define VOCAB  30522
#define KSPLIT 8
#define K1LEN  192

#define VN_PAD 30720           // 240 * 128
#define KP     384             // 3 * 128 split-bf16 K
#define NKITER 6               // 384 / 64

// scratch
__device__ float g_Ag[SPANS * 2 * DIM];
__device__ float g_P[SPAN_L * DIM];
__device__ float g_Upart[KSPLIT * SPANS * DIM];
__device__ float g_h1[ROWS * DIM];
__device__ float g_pre2[ROWS * DIM];
__device__ float g_h2[ROWS * DIM];
__device__ float g_h3[ROWS * EMB];
__device__ __nv_bfloat16 g_A2[ROWS * KP];          // [5120][384]
__device__ __nv_bfloat16 g_B2[VN_PAD * KP];        // [30720][384] (pad rows 0)

// ---------------- packed f32x2 helpers ----------------
__device__ __forceinline__ unsigned long long pack2(float x, float y) {
    unsigned long long r;
    asm("mov.b64 %0, {%1, %2};" : "=l"(r)
        : "r"(__float_as_uint(x)), "r"(__float_as_uint(y)));
    return r;
}
__device__ __forceinline__ void unpack2(unsigned long long v, float& x, float& y) {
    unsigned a, b;
    asm("mov.b64 {%0, %1}, %2;" : "=r"(a), "=r"(b) : "l"(v));
    x = __uint_as_float(a);
    y = __uint_as_float(b);
}
__device__ __forceinline__ void fma2(unsigned long long& d,
                                     unsigned long long a, unsigned long long b) {
    asm("fma.rn.f32x2 %0, %1, %2, %0;" : "+l"(d) : "l"(a), "l"(b));
}

// ---------------- mma / ldmatrix / cp.async helpers ----------------
__device__ __forceinline__ uint32_t smem_u32(const void* p) {
    uint32_t a;
    asm("{ .reg .u64 t; cvta.to.shared.u64 t, %1; cvt.u32.u64 %0, t; }"
        : "=r"(a) : "l"(p));
    return a;
}
__device__ __forceinline__ void ldsm_x4(uint32_t& r0, uint32_t& r1,
                                        uint32_t& r2, uint32_t& r3, uint32_t addr) {
    asm volatile("ldmatrix.sync.aligned.m8n8.x4.shared.b16 {%0,%1,%2,%3}, [%4];"
                 : "=r"(r0), "=r"(r1), "=r"(r2), "=r"(r3) : "r"(addr));
}
__device__ __forceinline__ void mma16816(float* d, const uint32_t* a, const uint32_t* b) {
    asm volatile(
        "mma.sync.aligned.m16n8k16.row.col.f32.bf16.bf16.f32 "
        "{%0,%1,%2,%3}, {%4,%5,%6,%7}, {%8,%9}, {%0,%1,%2,%3};"
        : "+f"(d[0]), "+f"(d[1]), "+f"(d[2]), "+f"(d[3])
        : "r"(a[0]), "r"(a[1]), "r"(a[2]), "r"(a[3]), "r"(b[0]), "r"(b[1]));
}
__device__ __forceinline__ void cpasync16(uint32_t d, const void* g) {
    asm volatile("cp.async.cg.shared.global [%0], [%1], 16;" :: "r"(d), "l"(g) : "memory");
}

// ---------------------------------------------------------------------------
__global__ void __launch_bounds__(256) gather_kernel(const float* __restrict__ H,
                                                     const int* __restrict__ pairs) {
    int s = blockIdx.x;
    int b = s / NPAIR;
    int i0 = pairs[s * 2 + 0];
    int i1 = pairs[s * 2 + 1];
    const float* h0 = H + ((size_t)b * SEQ + i0) * DIM;
    const float* h1 = H + ((size_t)b * SEQ + i1) * DIM;
    float* dst = g_Ag + (size_t)s * (2 * DIM);
    for (int i = threadIdx.x; i < DIM; i += 256) {
        dst[i]       = h0[i];
        dst[DIM + i] = h1[i];
    }
}

__global__ void __launch_bounds__(DIM) posw_kernel(const float* __restrict__ pos_emb,
                                                   const float* __restrict__ W1,
                                                   const float* __restrict__ b1) {
    int l = blockIdx.x;
    int n = threadIdx.x;
    __shared__ float pe[PE];
    for (int i = threadIdx.x; i < PE; i += blockDim.x) pe[i] = pos_emb[l * PE + i];
    __syncthreads();
    float acc = b1[n];
    const float* Wc = W1 + (size_t)(2 * DIM) * DIM + n;
    #pragma unroll 4
    for (int k = 0; k < PE; ++k) acc = fmaf(pe[k], Wc[(size_t)k * DIM], acc);
    g_P[l * DIM + n] = acc;
}

// ---------------------------------------------------------------------------
// FFMA2 SGEMM body (small GEMMs)
// ---------------------------------------------------------------------------
template<int BM, int BN, int BK, int TM, int TN>
__device__ __forceinline__ void gemm_body(
    const float* __restrict__ A, int lda,
    const float* __restrict__ B, int ldb,
    const float* __restrict__ bias,
    float* __restrict__ C, int ldc, int klen)
{
    __shared__ float As[BK][BM];
    __shared__ float Bs[BK][BN];
    const int tid = threadIdx.x;
    const int tx = tid & 15;
    const int ty = tid >> 4;
    const int m0 = blockIdx.y * BM;
    const int n0 = blockIdx.x * BN;
    const int k0 = blockIdx.z * klen;

    unsigned long long acc[TM / 2][TN];
    #pragma unroll
    for (int i = 0; i < TM / 2; ++i)
        #pragma unroll
        for (int j = 0; j < TN; ++j) acc[i][j] = 0ull;

    for (int kk = 0; kk < klen; kk += BK) {
        #pragma unroll
        for (int i = 0; i < (BM * BK) / 1024; ++i) {
            int q   = tid + i * 256;
            int row = q / (BK / 4);
            int kc  = (q % (BK / 4)) * 4;
            float4 v = *(const float4*)&A[(size_t)(m0 + row) * lda + (k0 + kk + kc)];
            As[kc + 0][row] = v.x; As[kc + 1][row] = v.y;
            As[kc + 2][row] = v.z; As[kc + 3][row] = v.w;
        }
        #pragma unroll
        for (int i = 0; i < (BK * BN) / 1024; ++i) {
            int q  = tid + i * 256;
            int kr = q / (BN / 4);
            int nc = (q % (BN / 4)) * 4;
            *(float4*)&Bs[kr][nc] =
                *(const float4*)&B[(size_t)(k0 + kk + kr) * ldb + (n0 + nc)];
        }
        __syncthreads();

        #pragma unroll
        for (int k = 0; k < BK; ++k) {
            unsigned long long a2[TM / 2];
            #pragma unroll
            for (int i = 0; i < TM / 2; ++i)
                a2[i] = *(const unsigned long long*)&As[k][ty * TM + 2 * i];
            #pragma unroll
            for (int j = 0; j < TN; ++j) {
                float bv = Bs[k][tx * TN + j];
                unsigned long long b2 = pack2(bv, bv);
                #pragma unroll
                for (int i = 0; i < TM / 2; ++i) fma2(acc[i][j], a2[i], b2);
            }
        }
        __syncthreads();
    }

    #pragma unroll
    for (int j = 0; j < TN; ++j) {
        int n = n0 + tx * TN + j;
        float bv = bias ? bias[n] : 0.0f;
        #pragma unroll
        for (int i = 0; i < TM / 2; ++i) {
            float lo, hi;
            unpack2(acc[i][j], lo, hi);
            int m = m0 + ty * TM + 2 * i;
            C[(size_t)m * ldc + n]       = lo + bv;
            C[(size_t)(m + 1) * ldc + n] = hi + bv;
        }
    }
}

__global__ void __launch_bounds__(256) k_gemm_span(const float* __restrict__ W1) {
    gemm_body<64, 128, 16, 4, 8>(
        g_Ag, 2 * DIM, W1, DIM, nullptr,
        g_Upart + (size_t)blockIdx.z * SPANS * DIM, DIM, K1LEN);
}
__global__ void __launch_bounds__(256) k_gemm_h1W2(const float* __restrict__ W2) {
    gemm_body<128, 128, 16, 8, 8>(g_h1, DIM, W2, DIM, nullptr, g_pre2, DIM, DIM);
}
__global__ void __launch_bounds__(256) k_gemm_proj(const float* __restrict__ Wp,
                                                   const float* __restrict__ bp) {
    gemm_body<64, 128, 16, 4, 8>(g_h2, DIM, Wp, EMB, bp, g_h3, EMB, DIM);
}

// ---------------------------------------------------------------------------
// split-bf16 conversions:  A' = [hi | hi | lo],  B' = [hi | lo | hi]
// ---------------------------------------------------------------------------
__global__ void __launch_bounds__(256) conv_A(void) {
    int idx = blockIdx.x * 256 + threadIdx.x;
    if (idx >= ROWS * EMB) return;
    int m = idx / EMB, k = idx % EMB;
    float x = g_h3[idx];
    __nv_bfloat16 hi = __float2bfloat16_rn(x);
    __nv_bfloat16 lo = __float2bfloat16_rn(x - __bfloat162float(hi));
    __nv_bfloat16* d = g_A2 + (size_t)m * KP + k;
    d[0]   = hi;
    d[128] = hi;
    d[256] = lo;
}
__global__ void __launch_bounds__(256) conv_B(const float* __restrict__ Wdec) {
    int idx = blockIdx.x * 256 + threadIdx.x;
    if (idx >= VOCAB * EMB) return;
    int n = idx / EMB, k = idx % EMB;
    float x = Wdec[idx];
    __nv_bfloat16 hi = __float2bfloat16_rn(x);
    __nv_bfloat16 lo = __float2bfloat16_rn(x - __bfloat162float(hi));
    __nv_bfloat16* d = g_B2 + (size_t)n * KP + k;
    d[0]   = hi;
    d[128] = lo;
    d[256] = hi;
}

// ---------------------------------------------------------------------------
// vocab GEMM via mma.sync bf16:
//   out[5120][30522] = A'[5120][384] @ B'[30720][384]^T
// CTA tile 128x128, BK=64 (128B rows, XOR-swizzled smem), 8 warps of 64x32.
// ---------------------------------------------------------------------------
__global__ void __launch_bounds__(256, 2) k_vocab_mma(float* __restrict__ out) {
    __shared__ __align__(1024) __nv_bfloat16 As[128 * 64];
    __shared__ __align__(1024) __nv_bfloat16 Bs[128 * 64];
    const int tid  = threadIdx.x;
    const int lane = tid & 31;
    const int wid  = tid >> 5;
    const int wm   = wid & 1;        // 2 warps along M
    const int wn   = wid >> 1;       // 4 warps along N
    const int m0 = blockIdx.y * 128;
    const int n0 = blockIdx.x * 128;
    const uint32_t sA = smem_u32(As);
    const uint32_t sB = smem_u32(Bs);

    float acc[4][4][4];
    #pragma unroll
    for (int i = 0; i < 4; ++i)
        #pragma unroll
        for (int j = 0; j < 4; ++j)
            #pragma unroll
            for (int q = 0; q < 4; ++q) acc[i][j][q] = 0.f;

    const int lrow   = tid >> 3;     // 0..31
    const int lchunk = tid & 7;      // 16B chunk within 128B row

    // hoisted ldmatrix lane geometry
    const int a_rsub = (lane & 7) + ((lane >> 3) & 1) * 8;   // row within 16
    const int a_koff = lane >> 4;                            // chunk offset 0/1
    const int b_rsub = ((lane >> 4) & 1) * 8 + (lane & 7);
    const int b_koff = (lane >> 3) & 1;

    for (int kc = 0; kc < NKITER; ++kc) {
        if (kc) __syncthreads();
        #pragma unroll
        for (int i = 0; i < 4; ++i) {
            int row = lrow + i * 32;
            cpasync16(sA + row * 128 + ((lchunk ^ (row & 7)) << 4),
                      g_A2 + (size_t)(m0 + row) * KP + kc * 64 + lchunk * 8);
        }
        #pragma unroll
        for (int i = 0; i < 4; ++i) {
            int row = lrow + i * 32;
            cpasync16(sB + row * 128 + ((lchunk ^ (row & 7)) << 4),
                      g_B2 + (size_t)(n0 + row) * KP + kc * 64 + lchunk * 8);
        }
        asm volatile("cp.async.commit_group;" ::: "memory");
        asm volatile("cp.async.wait_group 0;" ::: "memory");
        __syncthreads();

        #pragma unroll
        for (int ks = 0; ks < 4; ++ks) {
            uint32_t a[4][4];
            #pragma unroll
            for (int i = 0; i < 4; ++i) {
                int row = wm * 64 + i * 16 + a_rsub;
                int chunk = ks * 2 + a_koff;
                ldsm_x4(a[i][0], a[i][1], a[i][2], a[i][3],
                        sA + row * 128 + ((chunk ^ (row & 7)) << 4));
            }
            #pragma unroll
            for (int h = 0; h < 2; ++h) {
                uint32_t b[4];
                int row = wn * 32 + h * 16 + b_rsub;
                int chunk = ks * 2 + b_koff;
                ldsm_x4(b[0], b[1], b[2], b[3],
                        sB + row * 128 + ((chunk ^ (row & 7)) << 4));
                #pragma unroll
                for (int i = 0; i < 4; ++i) {
                    mma16816(acc[i][2 * h],     a[i], b);
                    mma16816(acc[i][2 * h + 1], a[i], b + 2);
                }
            }
        }
    }

    // epilogue
    const int tq = lane >> 2, tr = lane & 3;
    #pragma unroll
    for (int i = 0; i < 4; ++i) {
        int row = m0 + wm * 64 + i * 16 + tq;
        #pragma unroll
        for (int j = 0; j < 4; ++j) {
            int col = n0 + wn * 32 + j * 8 + tr * 2;
            if (col >= VOCAB) continue;
            *(float2*)(out + (size_t)row * VOCAB + col) =
                make_float2(acc[i][j][0], acc[i][j][1]);
            *(float2*)(out + (size_t)(row + 8) * VOCAB + col) =
                make_float2(acc[i][j][2], acc[i][j][3]);
        }
    }
}

// ---------------------------------------------------------------------------
// gelu + layernorm fusions
// ---------------------------------------------------------------------------
__device__ __forceinline__ float gelu_exact(float x) {
    return 0.5f * x * (1.0f + erff(x * 0.70710678118654752f));
}

__global__ void __launch_bounds__(256) fuse_ln1(const float* __restrict__ g,
                                                const float* __restrict__ be) {
    int r = blockIdx.x;
    int s = r / SPAN_L;
    int l = r % SPAN_L;
    __shared__ float shs[8], shq[8];
    float v[3];
    float sum = 0.f, sq = 0.f;
    #pragma unroll
    for (int j = 0; j < 3; ++j) {
        int n = threadIdx.x + j * 256;
        float x = g_P[l * DIM + n];
        #pragma unroll
        for (int z = 0; z < KSPLIT; ++z)
            x += g_Upart[(size_t)z * SPANS * DIM + (size_t)s * DIM + n];
        float ge = gelu_exact(x);
        v[j] = ge;
        sum += ge;
        sq  += ge * ge;
    }
    #pragma unroll
    for (int o = 16; o > 0; o >>= 1) {
        sum += __shfl_xor_sync(0xffffffffu, sum, o);
        sq  += __shfl_xor_sync(0xffffffffu, sq, o);
    }
    if ((threadIdx.x & 31) == 0) { shs[threadIdx.x >> 5] = sum; shq[threadIdx.x >> 5] = sq; }
    __syncthreads();
    float ts = 0.f, tq = 0.f;
    #pragma unroll
    for (int w = 0; w < 8; ++w) { ts += shs[w]; tq += shq[w]; }
    float mean = ts * (1.0f / DIM);
    float var  = tq * (1.0f / DIM) - mean * mean;
    float rstd = rsqrtf(var + 1e-12f);
    #pragma unroll
    for (int j = 0; j < 3; ++j) {
        int n = threadIdx.x + j * 256;
        g_h1[(size_t)r * DIM + n] = (v[j] - mean) * rstd * g[n] + be[n];
    }
}

__global__ void __launch_bounds__(256) fuse_ln2(const float* __restrict__ bias,
                                                const float* __restrict__ g,
                                                const float* __restrict__ be) {
    int r = blockIdx.x;
    __shared__ float shs[8], shq[8];
    float v[3];
    float sum = 0.f, sq = 0.f;
    #pragma unroll
    for (int j = 0; j < 3; ++j) {
        int n = threadIdx.x + j * 256;
        float x = g_pre2[(size_t)r * DIM + n] + bias[n];
        float ge = gelu_exact(x);
        v[j] = ge;
        sum += ge;
        sq  += ge * ge;
    }
    #pragma unroll
    for (int o = 16; o > 0; o >>= 1) {
        sum += __shfl_xor_sync(0xffffffffu, sum, o);
        sq  += __shfl_xor_sync(0xffffffffu, sq, o);
    }
    if ((threadIdx.x & 31) == 0) { shs[threadIdx.x >> 5] = sum; shq[threadIdx.x >> 5] = sq; }
    __syncthreads();
    float ts = 0.f, tq = 0.f;
    #pragma unroll
    for (int w = 0; w < 8; ++w) { ts += shs[w]; tq += shq[w]; }
    float mean = ts * (1.0f / DIM);
    float var  = tq * (1.0f / DIM) - mean * mean;
    float rstd = rsqrtf(var + 1e-12f);
    #pragma unroll
    for (int j = 0; j < 3; ++j) {
        int n = threadIdx.x + j * 256;
        g_h2[(size_t)r * DIM + n] = (v[j] - mean) * rstd * g[n] + be[n];
    }
}

// ---------------------------------------------------------------------------
extern "C" void kernel_launch(void* const* d_in, const int* in_sizes, int n_in,
                              void* d_out, int out_size) {
    const float* H       = (const float*)d_in[0];
    const int*   pairs   = (const int*)  d_in[1];
    const float* pos_emb = (const float*)d_in[2];
    const float* W1      = (const float*)d_in[3];
    const float* b1      = (const float*)d_in[4];
    const float* g1      = (const float*)d_in[5];
    const float* be1     = (const float*)d_in[6];
    const float* W2      = (const float*)d_in[7];
    const float* b2      = (const float*)d_in[8];
    const float* g2      = (const float*)d_in[9];
    const float* be2     = (const float*)d_in[10];
    const float* Wp      = (const float*)d_in[11];
    const float* bp      = (const float*)d_in[12];
    const float* Wdec    = (const float*)d_in[13];
    float* out = (float*)d_out;

    gather_kernel<<<SPANS, 256>>>(H, pairs);
    posw_kernel<<<SPAN_L, DIM>>>(pos_emb, W1, b1);
    conv_B<<<(VOCAB * EMB + 255) / 256, 256>>>(Wdec);
    k_gemm_span<<<dim3(DIM / 128, SPANS / 64, KSPLIT), 256>>>(W1);
    fuse_ln1<<<ROWS, 256>>>(g1, be1);
    k_gemm_h1W2<<<dim3(DIM / 128, ROWS / 128, 1), 256>>>(W2);
    fuse_ln2<<<ROWS, 256>>>(b2, g2, be2);
    k_gemm_proj<<<dim3(1, ROWS / 64, 1), 256>>>(Wp, bp);
    conv_A<<<(ROWS * EMB + 255) / 256, 256>>>();
    k_vocab_mma<<<dim3(VN_PAD / 128, ROWS / 128), 256>>>(out);
}

// round 8
// speedup vs baseline: 3.0225x; 1.3157x over previous
#include <cuda_runtime.h>
#include <cuda_bf16.h>
#include <cstdint>
#include <cstddef>

// ---------------------------------------------------------------------------
// SpanElectraGeneratorPredictionHead — split-bf16 HMMA for all big GEMMs
// FIX vs rounds 5/6: __device__ globals are NEVER passed as kernel arguments
// from host code (host sees zero-filled ATS shadow). All HMMA kernels bind
// the globals inside device code via thin wrappers.
//
//   gather -> posw -> span GEMM (FFMA2, split-K 24) -> reduce_U
//   fuse_ln1 (writes split-bf16 h1')           A' = [hi|hi|lo]
//   HMMA  pre2 = h1' @ W2'   (K' = 2304)       B' = [hi|lo|hi]
//   fuse_ln2 (writes split-bf16 h2')
//   HMMA  h3p  = h2' @ Wp'   (split-K=3 partials over K'=2304)
//   conv_A: A2 = split(sum h3p + bp)
//   HMMA  out  = A2 @ B2^T   (vocab, K' = 384)
// ---------------------------------------------------------------------------

#define DIM    768
#define SEQ    512
#define NPAIR  32
#define SPANS  256
#define PE     200
#define SPAN_L 20
#define ROWS   5120
#define EMB    128
#define VOCAB  30522
#define KSPLIT 24
#define K1LEN  64

#define VN_PAD 30720
#define KPV    384              // vocab K'
#define KP2    2304             // 3*768 K' for dim-GEMMs

// scratch
__device__ float g_Ag[SPANS * 2 * DIM];
__device__ float g_P[SPAN_L * DIM];
__device__ float g_Upart[KSPLIT * SPANS * DIM];
__device__ float g_U[SPANS * DIM];
__device__ float g_pre2[ROWS * DIM];
__device__ float g_h3p[3 * ROWS * EMB];
__device__ __nv_bfloat16 g_h1s[ROWS * KP2];        // split h1
__device__ __nv_bfloat16 g_h2s[ROWS * KP2];        // split h2
__device__ __nv_bfloat16 g_W2s[DIM * KP2];         // split W2^T
__device__ __nv_bfloat16 g_Wps[EMB * KP2];         // split Wp^T
__device__ __nv_bfloat16 g_A2[ROWS * KPV];
__device__ __nv_bfloat16 g_B2[VN_PAD * KPV];       // pad rows stay 0

// ---------------- packed f32x2 helpers ----------------
__device__ __forceinline__ unsigned long long pack2(float x, float y) {
    unsigned long long r;
    asm("mov.b64 %0, {%1, %2};" : "=l"(r)
        : "r"(__float_as_uint(x)), "r"(__float_as_uint(y)));
    return r;
}
__device__ __forceinline__ void unpack2(unsigned long long v, float& x, float& y) {
    unsigned a, b;
    asm("mov.b64 {%0, %1}, %2;" : "=r"(a), "=r"(b) : "l"(v));
    x = __uint_as_float(a);
    y = __uint_as_float(b);
}
__device__ __forceinline__ void fma2(unsigned long long& d,
                                     unsigned long long a, unsigned long long b) {
    asm("fma.rn.f32x2 %0, %1, %2, %0;" : "+l"(d) : "l"(a), "l"(b));
}

// ---------------- mma / ldmatrix / cp.async helpers ----------------
__device__ __forceinline__ uint32_t smem_u32(const void* p) {
    uint32_t a;
    asm("{ .reg .u64 t; cvta.to.shared.u64 t, %1; cvt.u32.u64 %0, t; }"
        : "=r"(a) : "l"(p));
    return a;
}
__device__ __forceinline__ void ldsm_x4(uint32_t& r0, uint32_t& r1,
                                        uint32_t& r2, uint32_t& r3, uint32_t addr) {
    asm volatile("ldmatrix.sync.aligned.m8n8.x4.shared.b16 {%0,%1,%2,%3}, [%4];"
                 : "=r"(r0), "=r"(r1), "=r"(r2), "=r"(r3) : "r"(addr));
}
__device__ __forceinline__ void mma16816(float* d, const uint32_t* a, const uint32_t* b) {
    asm volatile(
        "mma.sync.aligned.m16n8k16.row.col.f32.bf16.bf16.f32 "
        "{%0,%1,%2,%3}, {%4,%5,%6,%7}, {%8,%9}, {%0,%1,%2,%3};"
        : "+f"(d[0]), "+f"(d[1]), "+f"(d[2]), "+f"(d[3])
        : "r"(a[0]), "r"(a[1]), "r"(a[2]), "r"(a[3]), "r"(b[0]), "r"(b[1]));
}
__device__ __forceinline__ void cpasync16(uint32_t d, const void* g) {
    asm volatile("cp.async.cg.shared.global [%0], [%1], 16;" :: "r"(d), "l"(g) : "memory");
}

// ---------------------------------------------------------------------------
__global__ void __launch_bounds__(256) gather_kernel(const float* __restrict__ H,
                                                     const int* __restrict__ pairs) {
    int s = blockIdx.x;
    int b = s / NPAIR;
    int i0 = pairs[s * 2 + 0];
    int i1 = pairs[s * 2 + 1];
    const float* h0 = H + ((size_t)b * SEQ + i0) * DIM;
    const float* h1 = H + ((size_t)b * SEQ + i1) * DIM;
    float* dst = g_Ag + (size_t)s * (2 * DIM);
    for (int i = threadIdx.x; i < DIM; i += 256) {
        dst[i]       = h0[i];
        dst[DIM + i] = h1[i];
    }
}

__global__ void __launch_bounds__(DIM) posw_kernel(const float* __restrict__ pos_emb,
                                                   const float* __restrict__ W1,
                                                   const float* __restrict__ b1) {
    int l = blockIdx.x;
    int n = threadIdx.x;
    __shared__ float pe[PE];
    for (int i = threadIdx.x; i < PE; i += blockDim.x) pe[i] = pos_emb[l * PE + i];
    __syncthreads();
    float acc = b1[n];
    const float* Wc = W1 + (size_t)(2 * DIM) * DIM + n;
    #pragma unroll 4
    for (int k = 0; k < PE; ++k) acc = fmaf(pe[k], Wc[(size_t)k * DIM], acc);
    g_P[l * DIM + n] = acc;
}

// ---------------------------------------------------------------------------
// FFMA2 SGEMM (span GEMM only)
// ---------------------------------------------------------------------------
template<int BM, int BN, int BK, int TM, int TN>
__device__ __forceinline__ void gemm_body(
    const float* __restrict__ A, int lda,
    const float* __restrict__ B, int ldb,
    float* __restrict__ C, int ldc, int klen)
{
    __shared__ float As[BK][BM];
    __shared__ float Bs[BK][BN];
    const int tid = threadIdx.x;
    const int tx = tid & 15;
    const int ty = tid >> 4;
    const int m0 = blockIdx.y * BM;
    const int n0 = blockIdx.x * BN;
    const int k0 = blockIdx.z * klen;

    unsigned long long acc[TM / 2][TN];
    #pragma unroll
    for (int i = 0; i < TM / 2; ++i)
        #pragma unroll
        for (int j = 0; j < TN; ++j) acc[i][j] = 0ull;

    for (int kk = 0; kk < klen; kk += BK) {
        #pragma unroll
        for (int i = 0; i < (BM * BK) / 1024; ++i) {
            int q   = tid + i * 256;
            int row = q / (BK / 4);
            int kc  = (q % (BK / 4)) * 4;
            float4 v = *(const float4*)&A[(size_t)(m0 + row) * lda + (k0 + kk + kc)];
            As[kc + 0][row] = v.x; As[kc + 1][row] = v.y;
            As[kc + 2][row] = v.z; As[kc + 3][row] = v.w;
        }
        #pragma unroll
        for (int i = 0; i < (BK * BN) / 1024; ++i) {
            int q  = tid + i * 256;
            int kr = q / (BN / 4);
            int nc = (q % (BN / 4)) * 4;
            *(float4*)&Bs[kr][nc] =
                *(const float4*)&B[(size_t)(k0 + kk + kr) * ldb + (n0 + nc)];
        }
        __syncthreads();

        #pragma unroll
        for (int k = 0; k < BK; ++k) {
            unsigned long long a2[TM / 2];
            #pragma unroll
            for (int i = 0; i < TM / 2; ++i)
                a2[i] = *(const unsigned long long*)&As[k][ty * TM + 2 * i];
            #pragma unroll
            for (int j = 0; j < TN; ++j) {
                float bv = Bs[k][tx * TN + j];
                unsigned long long b2 = pack2(bv, bv);
                #pragma unroll
                for (int i = 0; i < TM / 2; ++i) fma2(acc[i][j], a2[i], b2);
            }
        }
        __syncthreads();
    }

    #pragma unroll
    for (int j = 0; j < TN; ++j) {
        int n = n0 + tx * TN + j;
        #pragma unroll
        for (int i = 0; i < TM / 2; ++i) {
            float lo, hi;
            unpack2(acc[i][j], lo, hi);
            int m = m0 + ty * TM + 2 * i;
            C[(size_t)m * ldc + n]       = lo;
            C[(size_t)(m + 1) * ldc + n] = hi;
        }
    }
}

__global__ void __launch_bounds__(256) k_gemm_span(const float* __restrict__ W1) {
    gemm_body<64, 128, 16, 4, 8>(
        g_Ag, 2 * DIM, W1, DIM,
        g_Upart + (size_t)blockIdx.z * SPANS * DIM, DIM, K1LEN);
}

__global__ void __launch_bounds__(256) reduce_U(void) {
    int idx = blockIdx.x * 256 + threadIdx.x;
    if (idx >= SPANS * DIM) return;
    float s = 0.f;
    #pragma unroll
    for (int z = 0; z < KSPLIT; ++z) s += g_Upart[(size_t)z * SPANS * DIM + idx];
    g_U[idx] = s;
}

// ---------------------------------------------------------------------------
// weight split conversions: B' = [hi | lo | hi] over K
// ---------------------------------------------------------------------------
__global__ void __launch_bounds__(256) conv_W2(const float* __restrict__ W2) {
    int idx = blockIdx.x * 256 + threadIdx.x;
    if (idx >= DIM * DIM) return;
    int k = idx / DIM, n = idx % DIM;
    float x = W2[idx];
    __nv_bfloat16 hi = __float2bfloat16_rn(x);
    __nv_bfloat16 lo = __float2bfloat16_rn(x - __bfloat162float(hi));
    __nv_bfloat16* d = g_W2s + (size_t)n * KP2 + k;
    d[0]    = hi;
    d[768]  = lo;
    d[1536] = hi;
}
__global__ void __launch_bounds__(256) conv_Wp(const float* __restrict__ Wp) {
    int idx = blockIdx.x * 256 + threadIdx.x;
    if (idx >= DIM * EMB) return;
    int k = idx / EMB, n = idx % EMB;
    float x = Wp[idx];
    __nv_bfloat16 hi = __float2bfloat16_rn(x);
    __nv_bfloat16 lo = __float2bfloat16_rn(x - __bfloat162float(hi));
    __nv_bfloat16* d = g_Wps + (size_t)n * KP2 + k;
    d[0]    = hi;
    d[768]  = lo;
    d[1536] = hi;
}
__global__ void __launch_bounds__(256) conv_B(const float* __restrict__ Wdec) {
    int idx = blockIdx.x * 256 + threadIdx.x;
    if (idx >= VOCAB * EMB) return;
    int n = idx / EMB, k = idx % EMB;
    float x = Wdec[idx];
    __nv_bfloat16 hi = __float2bfloat16_rn(x);
    __nv_bfloat16 lo = __float2bfloat16_rn(x - __bfloat162float(hi));
    __nv_bfloat16* d = g_B2 + (size_t)n * KPV + k;
    d[0]   = hi;
    d[128] = lo;
    d[256] = hi;
}
// A2 = split(sum_z h3p + bp) : A' = [hi | hi | lo]
__global__ void __launch_bounds__(256) conv_A(const float* __restrict__ bp) {
    int idx = blockIdx.x * 256 + threadIdx.x;
    if (idx >= ROWS * EMB) return;
    int m = idx / EMB, k = idx % EMB;
    float x = g_h3p[idx] + g_h3p[ROWS * EMB + idx] + g_h3p[2 * ROWS * EMB + idx] + bp[k];
    __nv_bfloat16 hi = __float2bfloat16_rn(x);
    __nv_bfloat16 lo = __float2bfloat16_rn(x - __bfloat162float(hi));
    __nv_bfloat16* d = g_A2 + (size_t)m * KPV + k;
    d[0]   = hi;
    d[128] = hi;
    d[256] = lo;
}

// ---------------------------------------------------------------------------
// Split-bf16 HMMA GEMM body (static smem, single-buffered, round-4 proven).
// Called ONLY from device code; A/B/C bind to __device__ globals in wrappers.
// CTA tile 128x128, BK=64 (128B rows, XOR swizzle), 8 warps of 64x32.
// ---------------------------------------------------------------------------
template<int KROW, int NKI, bool BOUNDN>
__device__ __forceinline__ void hmma_body(
    const __nv_bfloat16* __restrict__ A,
    const __nv_bfloat16* __restrict__ B,
    float* __restrict__ C, int ldc, int ncols, int kbase)
{
    __shared__ __align__(1024) __nv_bfloat16 As[128 * 64];
    __shared__ __align__(1024) __nv_bfloat16 Bs[128 * 64];
    const int tid  = threadIdx.x;
    const int lane = tid & 31;
    const int wid  = tid >> 5;
    const int wm   = wid & 1;
    const int wn   = wid >> 1;
    const int m0 = blockIdx.y * 128;
    const int n0 = blockIdx.x * 128;
    const uint32_t sA = smem_u32(As);
    const uint32_t sB = smem_u32(Bs);

    float acc[4][4][4];
    #pragma unroll
    for (int i = 0; i < 4; ++i)
        #pragma unroll
        for (int j = 0; j < 4; ++j)
            #pragma unroll
            for (int q = 0; q < 4; ++q) acc[i][j][q] = 0.f;

    const int lrow   = tid >> 3;
    const int lchunk = tid & 7;
    const uint32_t swz = (uint32_t)((lchunk ^ (lrow & 7)) << 4);

    const int a_rsub = (lane & 7) + ((lane >> 3) & 1) * 8;
    const int a_koff = lane >> 4;
    const int b_rsub = ((lane >> 4) & 1) * 8 + (lane & 7);
    const int b_koff = (lane >> 3) & 1;

    for (int kc = 0; kc < NKI; ++kc) {
        if (kc) __syncthreads();
        {
            const __nv_bfloat16* ga =
                A + (size_t)(m0 + lrow) * KROW + kbase + kc * 64 + lchunk * 8;
            const __nv_bfloat16* gb =
                B + (size_t)(n0 + lrow) * KROW + kbase + kc * 64 + lchunk * 8;
            #pragma unroll
            for (int i = 0; i < 4; ++i) {
                uint32_t off = (uint32_t)(lrow + i * 32) * 128u + swz;
                cpasync16(sA + off, ga + (size_t)i * 32 * KROW);
                cpasync16(sB + off, gb + (size_t)i * 32 * KROW);
            }
        }
        asm volatile("cp.async.commit_group;" ::: "memory");
        asm volatile("cp.async.wait_group 0;" ::: "memory");
        __syncthreads();

        #pragma unroll
        for (int ks = 0; ks < 4; ++ks) {
            uint32_t a[4][4];
            #pragma unroll
            for (int i = 0; i < 4; ++i) {
                int row = wm * 64 + i * 16 + a_rsub;
                int chunk = ks * 2 + a_koff;
                ldsm_x4(a[i][0], a[i][1], a[i][2], a[i][3],
                        sA + row * 128 + ((chunk ^ (row & 7)) << 4));
            }
            #pragma unroll
            for (int h = 0; h < 2; ++h) {
                uint32_t b[4];
                int row = wn * 32 + h * 16 + b_rsub;
                int chunk = ks * 2 + b_koff;
                ldsm_x4(b[0], b[1], b[2], b[3],
                        sB + row * 128 + ((chunk ^ (row & 7)) << 4));
                #pragma unroll
                for (int i = 0; i < 4; ++i) {
                    mma16816(acc[i][2 * h],     a[i], b);
                    mma16816(acc[i][2 * h + 1], a[i], b + 2);
                }
            }
        }
    }

    const int tq = lane >> 2, tr = lane & 3;
    #pragma unroll
    for (int i = 0; i < 4; ++i) {
        int row = m0 + wm * 64 + i * 16 + tq;
        #pragma unroll
        for (int j = 0; j < 4; ++j) {
            int col = n0 + wn * 32 + j * 8 + tr * 2;
            if (BOUNDN && col >= ncols) continue;
            *(float2*)(C + (size_t)row * ldc + col) =
                make_float2(acc[i][j][0], acc[i][j][1]);
            *(float2*)(C + (size_t)(row + 8) * ldc + col) =
                make_float2(acc[i][j][2], acc[i][j][3]);
        }
    }
}

// wrappers — globals bound in DEVICE code (host never sees their addresses)
__global__ void __launch_bounds__(256, 2) k_hmma_gemm2(void) {
    hmma_body<KP2, 36, false>(g_h1s, g_W2s, g_pre2, DIM, DIM, 0);
}
__global__ void __launch_bounds__(256, 2) k_hmma_proj(void) {
    hmma_body<KP2, 12, false>(g_h2s, g_Wps,
                              g_h3p + (size_t)blockIdx.z * ROWS * EMB,
                              EMB, EMB, blockIdx.z * 12 * 64);
}
__global__ void __launch_bounds__(256, 2) k_hmma_vocab(float* __restrict__ out) {
    hmma_body<KPV, 6, true>(g_A2, g_B2, out, VOCAB, VOCAB, 0);
}

// ---------------------------------------------------------------------------
// gelu + layernorm fusions — write split-bf16 A' = [hi|hi|lo]
// ---------------------------------------------------------------------------
__device__ __forceinline__ float gelu_exact(float x) {
    return 0.5f * x * (1.0f + erff(x * 0.70710678118654752f));
}
__device__ __forceinline__ void store_split(__nv_bfloat16* rowp, int n, float x) {
    __nv_bfloat16 hi = __float2bfloat16_rn(x);
    __nv_bfloat16 lo = __float2bfloat16_rn(x - __bfloat162float(hi));
    rowp[n]        = hi;
    rowp[768 + n]  = hi;
    rowp[1536 + n] = lo;
}

__global__ void __launch_bounds__(256) fuse_ln1(const float* __restrict__ g,
                                                const float* __restrict__ be) {
    int r = blockIdx.x;
    int s = r / SPAN_L;
    int l = r % SPAN_L;
    __shared__ float shs[8], shq[8];
    float v[3];
    float sum = 0.f, sq = 0.f;
    #pragma unroll
    for (int j = 0; j < 3; ++j) {
        int n = threadIdx.x + j * 256;
        float x = g_P[l * DIM + n] + g_U[s * DIM + n];
        float ge = gelu_exact(x);
        v[j] = ge;
        sum += ge;
        sq  += ge * ge;
    }
    #pragma unroll
    for (int o = 16; o > 0; o >>= 1) {
        sum += __shfl_xor_sync(0xffffffffu, sum, o);
        sq  += __shfl_xor_sync(0xffffffffu, sq, o);
    }
    if ((threadIdx.x & 31) == 0) { shs[threadIdx.x >> 5] = sum; shq[threadIdx.x >> 5] = sq; }
    __syncthreads();
    float ts = 0.f, tq = 0.f;
    #pragma unroll
    for (int w = 0; w < 8; ++w) { ts += shs[w]; tq += shq[w]; }
    float mean = ts * (1.0f / DIM);
    float var  = tq * (1.0f / DIM) - mean * mean;
    float rstd = rsqrtf(var + 1e-12f);
    __nv_bfloat16* rowp = g_h1s + (size_t)r * KP2;
    #pragma unroll
    for (int j = 0; j < 3; ++j) {
        int n = threadIdx.x + j * 256;
        store_split(rowp, n, (v[j] - mean) * rstd * g[n] + be[n]);
    }
}

__global__ void __launch_bounds__(256) fuse_ln2(const float* __restrict__ bias,
                                                const float* __restrict__ g,
                                                const float* __restrict__ be) {
    int r = blockIdx.x;
    __shared__ float shs[8], shq[8];
    float v[3];
    float sum = 0.f, sq = 0.f;
    #pragma unroll
    for (int j = 0; j < 3; ++j) {
        int n = threadIdx.x + j * 256;
        float x = g_pre2[(size_t)r * DIM + n] + bias[n];
        float ge = gelu_exact(x);
        v[j] = ge;
        sum += ge;
        sq  += ge * ge;
    }
    #pragma unroll
    for (int o = 16; o > 0; o >>= 1) {
        sum += __shfl_xor_sync(0xffffffffu, sum, o);
        sq  += __shfl_xor_sync(0xffffffffu, sq, o);
    }
    if ((threadIdx.x & 31) == 0) { shs[threadIdx.x >> 5] = sum; shq[threadIdx.x >> 5] = sq; }
    __syncthreads();
    float ts = 0.f, tq = 0.f;
    #pragma unroll
    for (int w = 0; w < 8; ++w) { ts += shs[w]; tq += shq[w]; }
    float mean = ts * (1.0f / DIM);
    float var  = tq * (1.0f / DIM) - mean * mean;
    float rstd = rsqrtf(var + 1e-12f);
    __nv_bfloat16* rowp = g_h2s + (size_t)r * KP2;
    #pragma unroll
    for (int j = 0; j < 3; ++j) {
        int n = threadIdx.x + j * 256;
        store_split(rowp, n, (v[j] - mean) * rstd * g[n] + be[n]);
    }
}

// ---------------------------------------------------------------------------
extern "C" void kernel_launch(void* const* d_in, const int* in_sizes, int n_in,
                              void* d_out, int out_size) {
    const float* H       = (const float*)d_in[0];
    const int*   pairs   = (const int*)  d_in[1];
    const float* pos_emb = (const float*)d_in[2];
    const float* W1      = (const float*)d_in[3];
    const float* b1      = (const float*)d_in[4];
    const float* g1      = (const float*)d_in[5];
    const float* be1     = (const float*)d_in[6];
    const float* W2      = (const float*)d_in[7];
    const float* b2      = (const float*)d_in[8];
    const float* g2      = (const float*)d_in[9];
    const float* be2     = (const float*)d_in[10];
    const float* Wp      = (const float*)d_in[11];
    const float* bp      = (const float*)d_in[12];
    const float* Wdec    = (const float*)d_in[13];
    float* out = (float*)d_out;

    gather_kernel<<<SPANS, 256>>>(H, pairs);
    posw_kernel<<<SPAN_L, DIM>>>(pos_emb, W1, b1);
    conv_B<<<(VOCAB * EMB + 255) / 256, 256>>>(Wdec);
    conv_W2<<<(DIM * DIM + 255) / 256, 256>>>(W2);
    conv_Wp<<<(DIM * EMB + 255) / 256, 256>>>(Wp);
    k_gemm_span<<<dim3(DIM / 128, SPANS / 64, KSPLIT), 256>>>(W1);
    reduce_U<<<(SPANS * DIM + 255) / 256, 256>>>();
    fuse_ln1<<<ROWS, 256>>>(g1, be1);
    k_hmma_gemm2<<<dim3(DIM / 128, ROWS / 128, 1), 256>>>();
    fuse_ln2<<<ROWS, 256>>>(b2, g2, be2);
    k_hmma_proj<<<dim3(1, ROWS / 128, 3), 256>>>();
    conv_A<<<(ROWS * EMB + 255) / 256, 256>>>(bp);
    k_hmma_vocab<<<dim3(VN_PAD / 128, ROWS / 128, 1), 256>>>(out);
}

// round 13
// speedup vs baseline: 3.3556x; 1.1102x over previous
#include <cuda_runtime.h>
#include <cuda_bf16.h>
#include <cstdint>
#include <cstddef>

// ---------------------------------------------------------------------------
// SpanElectraGeneratorPredictionHead — split-bf16 HMMA, 2-stage pipelined
// RULE (learned round 5-8): never pass __device__ globals as kernel args from
// host (ATS reads the zero host shadow). Globals bind in device code only.
// ---------------------------------------------------------------------------

#define DIM    768
#define SEQ    512
#define NPAIR  32
#define SPANS  256
#define PE     200
#define SPAN_L 20
#define ROWS   5120
#define EMB    128
#define VOCAB  30522
#define KSPLIT 24
#define K1LEN  64

#define VN_PAD 30720
#define KPV    384              // vocab K'
#define KP2    2304             // 3*768 K' for dim-GEMMs

#define HMMA_SMEM 65536         // 2 stages x (16KB A + 16KB B)

// scratch
__device__ float g_Ag[SPANS * 2 * DIM];
__device__ float g_P[SPAN_L * DIM];
__device__ float g_Upart[KSPLIT * SPANS * DIM];
__device__ float g_U[SPANS * DIM];
__device__ float g_pre2[ROWS * DIM];
__device__ float g_h3p[3 * ROWS * EMB];
__device__ __nv_bfloat16 g_h1s[ROWS * KP2];
__device__ __nv_bfloat16 g_h2s[ROWS * KP2];
__device__ __nv_bfloat16 g_W2s[DIM * KP2];
__device__ __nv_bfloat16 g_Wps[EMB * KP2];
__device__ __nv_bfloat16 g_A2[ROWS * KPV];
__device__ __nv_bfloat16 g_B2[VN_PAD * KPV];       // pad rows stay 0

// ---------------- packed f32x2 helpers ----------------
__device__ __forceinline__ unsigned long long pack2(float x, float y) {
    unsigned long long r;
    asm("mov.b64 %0, {%1, %2};" : "=l"(r)
        : "r"(__float_as_uint(x)), "r"(__float_as_uint(y)));
    return r;
}
__device__ __forceinline__ void unpack2(unsigned long long v, float& x, float& y) {
    unsigned a, b;
    asm("mov.b64 {%0, %1}, %2;" : "=r"(a), "=r"(b) : "l"(v));
    x = __uint_as_float(a);
    y = __uint_as_float(b);
}
__device__ __forceinline__ void fma2(unsigned long long& d,
                                     unsigned long long a, unsigned long long b) {
    asm("fma.rn.f32x2 %0, %1, %2, %0;" : "+l"(d) : "l"(a), "l"(b));
}

// ---------------- mma / ldmatrix / cp.async helpers ----------------
__device__ __forceinline__ uint32_t smem_u32(const void* p) {
    uint32_t a;
    asm("{ .reg .u64 t; cvta.to.shared.u64 t, %1; cvt.u32.u64 %0, t; }"
        : "=r"(a) : "l"(p));
    return a;
}
__device__ __forceinline__ void ldsm_x4(uint32_t& r0, uint32_t& r1,
                                        uint32_t& r2, uint32_t& r3, uint32_t addr) {
    asm volatile("ldmatrix.sync.aligned.m8n8.x4.shared.b16 {%0,%1,%2,%3}, [%4];"
                 : "=r"(r0), "=r"(r1), "=r"(r2), "=r"(r3) : "r"(addr));
}
__device__ __forceinline__ void mma16816(float* d, const uint32_t* a, const uint32_t* b) {
    asm volatile(
        "mma.sync.aligned.m16n8k16.row.col.f32.bf16.bf16.f32 "
        "{%0,%1,%2,%3}, {%4,%5,%6,%7}, {%8,%9}, {%0,%1,%2,%3};"
        : "+f"(d[0]), "+f"(d[1]), "+f"(d[2]), "+f"(d[3])
        : "r"(a[0]), "r"(a[1]), "r"(a[2]), "r"(a[3]), "r"(b[0]), "r"(b[1]));
}
__device__ __forceinline__ void cpasync16(uint32_t d, const void* g) {
    asm volatile("cp.async.cg.shared.global [%0], [%1], 16;" :: "r"(d), "l"(g) : "memory");
}

// ---------------------------------------------------------------------------
__global__ void __launch_bounds__(256) gather_kernel(const float* __restrict__ H,
                                                     const int* __restrict__ pairs) {
    int s = blockIdx.x;
    int b = s / NPAIR;
    int i0 = pairs[s * 2 + 0];
    int i1 = pairs[s * 2 + 1];
    const float* h0 = H + ((size_t)b * SEQ + i0) * DIM;
    const float* h1 = H + ((size_t)b * SEQ + i1) * DIM;
    float* dst = g_Ag + (size_t)s * (2 * DIM);
    for (int i = threadIdx.x; i < DIM; i += 256) {
        dst[i]       = h0[i];
        dst[DIM + i] = h1[i];
    }
}

__global__ void __launch_bounds__(DIM) posw_kernel(const float* __restrict__ pos_emb,
                                                   const float* __restrict__ W1,
                                                   const float* __restrict__ b1) {
    int l = blockIdx.x;
    int n = threadIdx.x;
    __shared__ float pe[PE];
    for (int i = threadIdx.x; i < PE; i += blockDim.x) pe[i] = pos_emb[l * PE + i];
    __syncthreads();
    float acc = b1[n];
    const float* Wc = W1 + (size_t)(2 * DIM) * DIM + n;
    #pragma unroll 4
    for (int k = 0; k < PE; ++k) acc = fmaf(pe[k], Wc[(size_t)k * DIM], acc);
    g_P[l * DIM + n] = acc;
}

// ---------------------------------------------------------------------------
// FFMA2 SGEMM (span GEMM only)
// ---------------------------------------------------------------------------
template<int BM, int BN, int BK, int TM, int TN>
__device__ __forceinline__ void gemm_body(
    const float* __restrict__ A, int lda,
    const float* __restrict__ B, int ldb,
    float* __restrict__ C, int ldc, int klen)
{
    __shared__ float As[BK][BM];
    __shared__ float Bs[BK][BN];
    const int tid = threadIdx.x;
    const int tx = tid & 15;
    const int ty = tid >> 4;
    const int m0 = blockIdx.y * BM;
    const int n0 = blockIdx.x * BN;
    const int k0 = blockIdx.z * klen;

    unsigned long long acc[TM / 2][TN];
    #pragma unroll
    for (int i = 0; i < TM / 2; ++i)
        #pragma unroll
        for (int j = 0; j < TN; ++j) acc[i][j] = 0ull;

    for (int kk = 0; kk < klen; kk += BK) {
        #pragma unroll
        for (int i = 0; i < (BM * BK) / 1024; ++i) {
            int q   = tid + i * 256;
            int row = q / (BK / 4);
            int kc  = (q % (BK / 4)) * 4;
            float4 v = *(const float4*)&A[(size_t)(m0 + row) * lda + (k0 + kk + kc)];
            As[kc + 0][row] = v.x; As[kc + 1][row] = v.y;
            As[kc + 2][row] = v.z; As[kc + 3][row] = v.w;
        }
        #pragma unroll
        for (int i = 0; i < (BK * BN) / 1024; ++i) {
            int q  = tid + i * 256;
            int kr = q / (BN / 4);
            int nc = (q % (BN / 4)) * 4;
            *(float4*)&Bs[kr][nc] =
                *(const float4*)&B[(size_t)(k0 + kk + kr) * ldb + (n0 + nc)];
        }
        __syncthreads();

        #pragma unroll
        for (int k = 0; k < BK; ++k) {
            unsigned long long a2[TM / 2];
            #pragma unroll
            for (int i = 0; i < TM / 2; ++i)
                a2[i] = *(const unsigned long long*)&As[k][ty * TM + 2 * i];
            #pragma unroll
            for (int j = 0; j < TN; ++j) {
                float bv = Bs[k][tx * TN + j];
                unsigned long long b2 = pack2(bv, bv);
                #pragma unroll
                for (int i = 0; i < TM / 2; ++i) fma2(acc[i][j], a2[i], b2);
            }
        }
        __syncthreads();
    }

    #pragma unroll
    for (int j = 0; j < TN; ++j) {
        int n = n0 + tx * TN + j;
        #pragma unroll
        for (int i = 0; i < TM / 2; ++i) {
            float lo, hi;
            unpack2(acc[i][j], lo, hi);
            int m = m0 + ty * TM + 2 * i;
            C[(size_t)m * ldc + n]       = lo;
            C[(size_t)(m + 1) * ldc + n] = hi;
        }
    }
}

__global__ void __launch_bounds__(256) k_gemm_span(const float* __restrict__ W1) {
    gemm_body<64, 128, 16, 4, 8>(
        g_Ag, 2 * DIM, W1, DIM,
        g_Upart + (size_t)blockIdx.z * SPANS * DIM, DIM, K1LEN);
}

__global__ void __launch_bounds__(256) reduce_U(void) {
    int idx = blockIdx.x * 256 + threadIdx.x;
    if (idx >= SPANS * DIM) return;
    float s = 0.f;
    #pragma unroll
    for (int z = 0; z < KSPLIT; ++z) s += g_Upart[(size_t)z * SPANS * DIM + idx];
    g_U[idx] = s;
}

// ---------------------------------------------------------------------------
// weight split conversions (transposed via smem -> coalesced stores along k)
//   B' = [hi | lo | hi] over K
// ---------------------------------------------------------------------------
__global__ void __launch_bounds__(256) conv_W2(const float* __restrict__ W2) {
    __shared__ float t[32][33];
    const int k0 = blockIdx.y * 32;
    const int n0 = blockIdx.x * 32;
    const int tx = threadIdx.x & 31;
    const int ty = threadIdx.x >> 5;      // 0..7
    #pragma unroll
    for (int i = 0; i < 4; ++i) {
        int k = ty + i * 8;
        t[k][tx] = W2[(size_t)(k0 + k) * DIM + n0 + tx];   // t[k][n]
    }
    __syncthreads();
    #pragma unroll
    for (int i = 0; i < 4; ++i) {
        int nn = ty + i * 8;
        float x = t[tx][nn];
        __nv_bfloat16 hi = __float2bfloat16_rn(x);
        __nv_bfloat16 lo = __float2bfloat16_rn(x - __bfloat162float(hi));
        __nv_bfloat16* d = g_W2s + (size_t)(n0 + nn) * KP2 + (k0 + tx);
        d[0]    = hi;
        d[768]  = lo;
        d[1536] = hi;
    }
}
__global__ void __launch_bounds__(256) conv_Wp(const float* __restrict__ Wp) {
    __shared__ float t[32][33];
    const int k0 = blockIdx.y * 32;
    const int n0 = blockIdx.x * 32;
    const int tx = threadIdx.x & 31;
    const int ty = threadIdx.x >> 5;
    #pragma unroll
    for (int i = 0; i < 4; ++i) {
        int k = ty + i * 8;
        t[k][tx] = Wp[(size_t)(k0 + k) * EMB + n0 + tx];
    }
    __syncthreads();
    #pragma unroll
    for (int i = 0; i < 4; ++i) {
        int nn = ty + i * 8;
        float x = t[tx][nn];
        __nv_bfloat16 hi = __float2bfloat16_rn(x);
        __nv_bfloat16 lo = __float2bfloat16_rn(x - __bfloat162float(hi));
        __nv_bfloat16* d = g_Wps + (size_t)(n0 + nn) * KP2 + (k0 + tx);
        d[0]    = hi;
        d[768]  = lo;
        d[1536] = hi;
    }
}
__global__ void __launch_bounds__(256) conv_B(const float* __restrict__ Wdec) {
    int idx = blockIdx.x * 256 + threadIdx.x;
    if (idx >= VOCAB * EMB) return;
    int n = idx / EMB, k = idx % EMB;
    float x = Wdec[idx];
    __nv_bfloat16 hi = __float2bfloat16_rn(x);
    __nv_bfloat16 lo = __float2bfloat16_rn(x - __bfloat162float(hi));
    __nv_bfloat16* d = g_B2 + (size_t)n * KPV + k;
    d[0]   = hi;
    d[128] = lo;
    d[256] = hi;
}
// A2 = split(sum_z h3p + bp) : A' = [hi | hi | lo]
__global__ void __launch_bounds__(256) conv_A(const float* __restrict__ bp) {
    int idx = blockIdx.x * 256 + threadIdx.x;
    if (idx >= ROWS * EMB) return;
    int m = idx / EMB, k = idx % EMB;
    float x = g_h3p[idx] + g_h3p[ROWS * EMB + idx] + g_h3p[2 * ROWS * EMB + idx] + bp[k];
    __nv_bfloat16 hi = __float2bfloat16_rn(x);
    __nv_bfloat16 lo = __float2bfloat16_rn(x - __bfloat162float(hi));
    __nv_bfloat16* d = g_A2 + (size_t)m * KPV + k;
    d[0]   = hi;
    d[128] = hi;
    d[256] = lo;
}

// ---------------------------------------------------------------------------
// Split-bf16 HMMA GEMM body — 2-stage cp.async pipeline, dynamic smem 64KB.
// CTA tile 128x128, BK=64 (128B rows, XOR swizzle), 8 warps of 64x32.
// ---------------------------------------------------------------------------
template<int KROW, int NKI, bool BOUNDN>
__device__ __forceinline__ void hmma_body(
    const __nv_bfloat16* __restrict__ A,
    const __nv_bfloat16* __restrict__ B,
    float* __restrict__ C, int ldc, int ncols, int kbase)
{
    extern __shared__ __align__(1024) char hsm[];
    const uint32_t sbase = smem_u32(hsm);
    const int tid  = threadIdx.x;
    const int lane = tid & 31;
    const int wid  = tid >> 5;
    const int wm   = wid & 1;
    const int wn   = wid >> 1;
    const int m0 = blockIdx.y * 128;
    const int n0 = blockIdx.x * 128;

    float acc[4][4][4];
    #pragma unroll
    for (int i = 0; i < 4; ++i)
        #pragma unroll
        for (int j = 0; j < 4; ++j)
            #pragma unroll
            for (int q = 0; q < 4; ++q) acc[i][j][q] = 0.f;

    const int lrow   = tid >> 3;
    const int lchunk = tid & 7;
    const uint32_t swz = (uint32_t)((lchunk ^ (lrow & 7)) << 4);

    const int a_rsub = (lane & 7) + ((lane >> 3) & 1) * 8;
    const int a_koff = lane >> 4;
    const int b_rsub = ((lane >> 4) & 1) * 8 + (lane & 7);
    const int b_koff = (lane >> 3) & 1;

    auto load_stage = [&](int kc) {
        const uint32_t sA = sbase + (uint32_t)(kc & 1) * 32768u;
        const uint32_t sB = sA + 16384u;
        const __nv_bfloat16* ga =
            A + (size_t)(m0 + lrow) * KROW + kbase + kc * 64 + lchunk * 8;
        const __nv_bfloat16* gb =
            B + (size_t)(n0 + lrow) * KROW + kbase + kc * 64 + lchunk * 8;
        #pragma unroll
        for (int i = 0; i < 4; ++i) {
            uint32_t off = (uint32_t)(lrow + i * 32) * 128u + swz;
            cpasync16(sA + off, ga + (size_t)i * 32 * KROW);
            cpasync16(sB + off, gb + (size_t)i * 32 * KROW);
        }
        asm volatile("cp.async.commit_group;" ::: "memory");
    };

    load_stage(0);

    for (int kc = 0; kc < NKI; ++kc) {
        if (kc + 1 < NKI) {
            load_stage(kc + 1);
            asm volatile("cp.async.wait_group 1;" ::: "memory");
        } else {
            asm volatile("cp.async.wait_group 0;" ::: "memory");
        }
        __syncthreads();

        const uint32_t sA = sbase + (uint32_t)(kc & 1) * 32768u;
        const uint32_t sB = sA + 16384u;
        #pragma unroll
        for (int ks = 0; ks < 4; ++ks) {
            uint32_t a[4][4];
            #pragma unroll
            for (int i = 0; i < 4; ++i) {
                int row = wm * 64 + i * 16 + a_rsub;
                int chunk = ks * 2 + a_koff;
                ldsm_x4(a[i][0], a[i][1], a[i][2], a[i][3],
                        sA + row * 128 + ((chunk ^ (row & 7)) << 4));
            }
            #pragma unroll
            for (int h = 0; h < 2; ++h) {
                uint32_t b[4];
                int row = wn * 32 + h * 16 + b_rsub;
                int chunk = ks * 2 + b_koff;
                ldsm_x4(b[0], b[1], b[2], b[3],
                        sB + row * 128 + ((chunk ^ (row & 7)) << 4));
                #pragma unroll
                for (int i = 0; i < 4; ++i) {
                    mma16816(acc[i][2 * h],     a[i], b);
                    mma16816(acc[i][2 * h + 1], a[i], b + 2);
                }
            }
        }
        __syncthreads();   // all warps done with this stage before it is refilled
    }

    const int tq = lane >> 2, tr = lane & 3;
    #pragma unroll
    for (int i = 0; i < 4; ++i) {
        int row = m0 + wm * 64 + i * 16 + tq;
        #pragma unroll
        for (int j = 0; j < 4; ++j) {
            int col = n0 + wn * 32 + j * 8 + tr * 2;
            if (BOUNDN && col >= ncols) continue;
            *(float2*)(C + (size_t)row * ldc + col) =
                make_float2(acc[i][j][0], acc[i][j][1]);
            *(float2*)(C + (size_t)(row + 8) * ldc + col) =
                make_float2(acc[i][j][2], acc[i][j][3]);
        }
    }
}

// wrappers — globals bound in DEVICE code (host never sees their addresses)
__global__ void __launch_bounds__(256, 2) k_hmma_gemm2(void) {
    hmma_body<KP2, 36, false>(g_h1s, g_W2s, g_pre2, DIM, DIM, 0);
}
__global__ void __launch_bounds__(256, 2) k_hmma_proj(void) {
    hmma_body<KP2, 12, false>(g_h2s, g_Wps,
                              g_h3p + (size_t)blockIdx.z * ROWS * EMB,
                              EMB, EMB, blockIdx.z * 12 * 64);
}
__global__ void __launch_bounds__(256, 2) k_hmma_vocab(float* __restrict__ out) {
    hmma_body<KPV, 6, true>(g_A2, g_B2, out, VOCAB, VOCAB, 0);
}

// ---------------------------------------------------------------------------
// gelu + layernorm fusions — write split-bf16 A' = [hi|hi|lo]
// ---------------------------------------------------------------------------
__device__ __forceinline__ float gelu_exact(float x) {
    return 0.5f * x * (1.0f + erff(x * 0.70710678118654752f));
}
__device__ __forceinline__ void store_split(__nv_bfloat16* rowp, int n, float x) {
    __nv_bfloat16 hi = __float2bfloat16_rn(x);
    __nv_bfloat16 lo = __float2bfloat16_rn(x - __bfloat162float(hi));
    rowp[n]        = hi;
    rowp[768 + n]  = hi;
    rowp[1536 + n] = lo;
}

__global__ void __launch_bounds__(256) fuse_ln1(const float* __restrict__ g,
                                                const float* __restrict__ be) {
    int r = blockIdx.x;
    int s = r / SPAN_L;
    int l = r % SPAN_L;
    __shared__ float shs[8], shq[8];
    float v[3];
    float sum = 0.f, sq = 0.f;
    #pragma unroll
    for (int j = 0; j < 3; ++j) {
        int n = threadIdx.x + j * 256;
        float x = g_P[l * DIM + n] + g_U[s * DIM + n];
        float ge = gelu_exact(x);
        v[j] = ge;
        sum += ge;
        sq  += ge * ge;
    }
    #pragma unroll
    for (int o = 16; o > 0; o >>= 1) {
        sum += __shfl_xor_sync(0xffffffffu, sum, o);
        sq  += __shfl_xor_sync(0xffffffffu, sq, o);
    }
    if ((threadIdx.x & 31) == 0) { shs[threadIdx.x >> 5] = sum; shq[threadIdx.x >> 5] = sq; }
    __syncthreads();
    float ts = 0.f, tq = 0.f;
    #pragma unroll
    for (int w = 0; w < 8; ++w) { ts += shs[w]; tq += shq[w]; }
    float mean = ts * (1.0f / DIM);
    float var  = tq * (1.0f / DIM) - mean * mean;
    float rstd = rsqrtf(var + 1e-12f);
    __nv_bfloat16* rowp = g_h1s + (size_t)r * KP2;
    #pragma unroll
    for (int j = 0; j < 3; ++j) {
        int n = threadIdx.x + j * 256;
        store_split(rowp, n, (v[j] - mean) * rstd * g[n] + be[n]);
    }
}

__global__ void __launch_bounds__(256) fuse_ln2(const float* __restrict__ bias,
                                                const float* __restrict__ g,
                                                const float* __restrict__ be) {
    int r = blockIdx.x;
    __shared__ float shs[8], shq[8];
    float v[3];
    float sum = 0.f, sq = 0.f;
    #pragma unroll
    for (int j = 0; j < 3; ++j) {
        int n = threadIdx.x + j * 256;
        float x = g_pre2[(size_t)r * DIM + n] + bias[n];
        float ge = gelu_exact(x);
        v[j] = ge;
        sum += ge;
        sq  += ge * ge;
    }
    #pragma unroll
    for (int o = 16; o > 0; o >>= 1) {
        sum += __shfl_xor_sync(0xffffffffu, sum, o);
        sq  += __shfl_xor_sync(0xffffffffu, sq, o);
    }
    if ((threadIdx.x & 31) == 0) { shs[threadIdx.x >> 5] = sum; shq[threadIdx.x >> 5] = sq; }
    __syncthreads();
    float ts = 0.f, tq = 0.f;
    #pragma unroll
    for (int w = 0; w < 8; ++w) { ts += shs[w]; tq += shq[w]; }
    float mean = ts * (1.0f / DIM);
    float var  = tq * (1.0f / DIM) - mean * mean;
    float rstd = rsqrtf(var + 1e-12f);
    __nv_bfloat16* rowp = g_h2s + (size_t)r * KP2;
    #pragma unroll
    for (int j = 0; j < 3; ++j) {
        int n = threadIdx.x + j * 256;
        store_split(rowp, n, (v[j] - mean) * rstd * g[n] + be[n]);
    }
}

// ---------------------------------------------------------------------------
extern "C" void kernel_launch(void* const* d_in, const int* in_sizes, int n_in,
                              void* d_out, int out_size) {
    const float* H       = (const float*)d_in[0];
    const int*   pairs   = (const int*)  d_in[1];
    const float* pos_emb = (const float*)d_in[2];
    const float* W1      = (const float*)d_in[3];
    const float* b1      = (const float*)d_in[4];
    const float* g1      = (const float*)d_in[5];
    const float* be1     = (const float*)d_in[6];
    const float* W2      = (const float*)d_in[7];
    const float* b2      = (const float*)d_in[8];
    const float* g2      = (const float*)d_in[9];
    const float* be2     = (const float*)d_in[10];
    const float* Wp      = (const float*)d_in[11];
    const float* bp      = (const float*)d_in[12];
    const float* Wdec    = (const float*)d_in[13];
    float* out = (float*)d_out;

    // unconditional (deterministic, no guards); host-side, not captured
    cudaFuncSetAttribute(k_hmma_gemm2,
                         cudaFuncAttributeMaxDynamicSharedMemorySize, HMMA_SMEM);
    cudaFuncSetAttribute(k_hmma_proj,
                         cudaFuncAttributeMaxDynamicSharedMemorySize, HMMA_SMEM);
    cudaFuncSetAttribute(k_hmma_vocab,
                         cudaFuncAttributeMaxDynamicSharedMemorySize, HMMA_SMEM);

    gather_kernel<<<SPANS, 256>>>(H, pairs);
    posw_kernel<<<SPAN_L, DIM>>>(pos_emb, W1, b1);
    conv_B<<<(VOCAB * EMB + 255) / 256, 256>>>(Wdec);
    conv_W2<<<dim3(DIM / 32, DIM / 32), 256>>>(W2);
    conv_Wp<<<dim3(EMB / 32, DIM / 32), 256>>>(Wp);
    k_gemm_span<<<dim3(DIM / 128, SPANS / 64, KSPLIT), 256>>>(W1);
    reduce_U<<<(SPANS * DIM + 255) / 256, 256>>>();
    fuse_ln1<<<ROWS, 256>>>(g1, be1);
    k_hmma_gemm2<<<dim3(DIM / 128, ROWS / 128, 1), 256, HMMA_SMEM>>>();
    fuse_ln2<<<ROWS, 256>>>(b2, g2, be2);
    k_hmma_proj<<<dim3(1, ROWS / 128, 3), 256, HMMA_SMEM>>>();
    conv_A<<<(ROWS * EMB + 255) / 256, 256>>>(bp);
    k_hmma_vocab<<<dim3(VN_PAD / 128, ROWS / 128, 1), 256, HMMA_SMEM>>>(out);
}